// round 1
// baseline (speedup 1.0000x reference)
#include <cuda_runtime.h>
#include <math_constants.h>

// Problem constants (match reference)
#define B_SZ 32
#define H_SZ 16
#define D_SZ 128
#define BLOCK_SIZE 16
#define MAX_BLOCKS 128
#define NUM_WARPS 8
#define SCALE 0.08838834764831845f  // 1/sqrt(128)

__global__ __launch_bounds__(256, 4)
void paged_attn_kernel(const float* __restrict__ q,
                       const float* __restrict__ kcache,
                       const float* __restrict__ vcache,
                       const int* __restrict__ block_tables,
                       const int* __restrict__ context_lens,
                       float* __restrict__ out) {
    const int h = blockIdx.x;
    const int b = blockIdx.y;
    const int tid = threadIdx.x;
    const int warp = tid >> 5;
    const int lane = tid & 31;

    __shared__ int s_bt[MAX_BLOCKS];
    __shared__ float s_m[NUM_WARPS];
    __shared__ float s_l[NUM_WARPS];
    __shared__ float s_acc[NUM_WARPS][D_SZ];

    const int ctx = context_lens[b];
    const int nblk = (ctx + BLOCK_SIZE - 1) / BLOCK_SIZE;
    for (int i = tid; i < nblk; i += 256) s_bt[i] = block_tables[b * MAX_BLOCKS + i];
    __syncthreads();

    // Load query slice: lane owns dims [4*lane, 4*lane+3]
    const float4* qp = (const float4*)(q + ((size_t)b * H_SZ + h) * D_SZ);
    const float4 qv = qp[lane];

    float m = -CUDART_INF_F;
    float l = 0.0f;
    float4 acc = make_float4(0.f, 0.f, 0.f, 0.f);

    for (int t = warp; t < ctx; t += NUM_WARPS) {
        const int blk = s_bt[t >> 4];
        const size_t base = (((size_t)blk * BLOCK_SIZE + (t & 15)) * H_SZ + h) * D_SZ;
        const float4 kk = ((const float4*)(kcache + base))[lane];
        const float4 vv = ((const float4*)(vcache + base))[lane];

        float d = qv.x * kk.x + qv.y * kk.y + qv.z * kk.z + qv.w * kk.w;
        d += __shfl_xor_sync(0xffffffffu, d, 16);
        d += __shfl_xor_sync(0xffffffffu, d, 8);
        d += __shfl_xor_sync(0xffffffffu, d, 4);
        d += __shfl_xor_sync(0xffffffffu, d, 2);
        d += __shfl_xor_sync(0xffffffffu, d, 1);
        const float s = d * SCALE;

        const float nm = fmaxf(m, s);
        const float c = __expf(m - nm);   // 0 on first iter (m = -inf)
        const float p = __expf(s - nm);
        l = l * c + p;
        acc.x = acc.x * c + p * vv.x;
        acc.y = acc.y * c + p * vv.y;
        acc.z = acc.z * c + p * vv.z;
        acc.w = acc.w * c + p * vv.w;
        m = nm;
    }

    if (lane == 0) { s_m[warp] = m; s_l[warp] = l; }
    ((float4*)s_acc[warp])[lane] = acc;
    __syncthreads();

    // Merge 8 warp-partials; 128 threads each own one output dim.
    if (tid < D_SZ) {
        float M = -CUDART_INF_F;
        #pragma unroll
        for (int w = 0; w < NUM_WARPS; ++w) M = fmaxf(M, s_m[w]);
        float L = 0.f, o = 0.f;
        #pragma unroll
        for (int w = 0; w < NUM_WARPS; ++w) {
            const float wgt = __expf(s_m[w] - M);  // 0 for empty warps (m=-inf)
            L += wgt * s_l[w];
            o += wgt * s_acc[w][tid];
        }
        out[((size_t)b * H_SZ + h) * D_SZ + tid] = o / L;
    }
}

extern "C" void kernel_launch(void* const* d_in, const int* in_sizes, int n_in,
                              void* d_out, int out_size) {
    const float* q  = (const float*)d_in[0];
    const float* kc = (const float*)d_in[1];
    const float* vc = (const float*)d_in[2];
    const int* bt   = (const int*)d_in[3];
    const int* cl   = (const int*)d_in[4];
    float* out      = (float*)d_out;

    dim3 grid(H_SZ, B_SZ);
    paged_attn_kernel<<<grid, 256>>>(q, kc, vc, bt, cl, out);
}

// round 2
// speedup vs baseline: 1.8767x; 1.8767x over previous
#include <cuda_runtime.h>
#include <math_constants.h>

#define B_SZ 32
#define H_SZ 16
#define D_SZ 128
#define BLOCK_SIZE 16
#define MAX_BLOCKS 128
#define NUM_WARPS 8
#define SCALE 0.08838834764831845f  // 1/sqrt(128)

#define CHUNK 512
#define NSPLIT 4   // 2048 / 512

// Split-KV partial results (unnormalized): per (b, h, split)
__device__ float g_m[B_SZ * H_SZ * NSPLIT];
__device__ float g_l[B_SZ * H_SZ * NSPLIT];
__device__ float g_acc[B_SZ * H_SZ * NSPLIT][D_SZ];

__device__ __forceinline__ float warp_sum(float d) {
    d += __shfl_xor_sync(0xffffffffu, d, 16);
    d += __shfl_xor_sync(0xffffffffu, d, 8);
    d += __shfl_xor_sync(0xffffffffu, d, 4);
    d += __shfl_xor_sync(0xffffffffu, d, 2);
    d += __shfl_xor_sync(0xffffffffu, d, 1);
    return d;
}

__global__ __launch_bounds__(256)
void paged_attn_partial(const float* __restrict__ q,
                        const float* __restrict__ kcache,
                        const float* __restrict__ vcache,
                        const int* __restrict__ block_tables,
                        const int* __restrict__ context_lens) {
    const int h = blockIdx.x;
    const int b = blockIdx.y;
    const int s = blockIdx.z;
    const int tid = threadIdx.x;
    const int warp = tid >> 5;
    const int lane = tid & 31;

    const int ctx = context_lens[b];
    const int c0 = s * CHUNK;
    if (c0 >= ctx) return;
    const int c1 = min(ctx, c0 + CHUNK);

    __shared__ int s_bt[CHUNK / BLOCK_SIZE];
    __shared__ float s_m[NUM_WARPS];
    __shared__ float s_l[NUM_WARPS];
    __shared__ float s_acc[NUM_WARPS][D_SZ];

    const int nblk = (c1 - c0 + BLOCK_SIZE - 1) / BLOCK_SIZE;
    for (int i = tid; i < nblk; i += 256)
        s_bt[i] = block_tables[b * MAX_BLOCKS + (c0 >> 4) + i];
    __syncthreads();

    const float4 qv = ((const float4*)(q + ((size_t)b * H_SZ + h) * D_SZ))[lane];

    float m = -CUDART_INF_F;
    float l = 0.0f;
    float4 acc = make_float4(0.f, 0.f, 0.f, 0.f);

    int t = c0 + warp;
    // 4-token unrolled main loop: 8 float4 loads in flight before use
    for (; t + 24 < c1; t += 32) {
        const int tl0 = t - c0, tl1 = tl0 + 8, tl2 = tl0 + 16, tl3 = tl0 + 24;
        const size_t b0 = (((size_t)s_bt[tl0 >> 4] * BLOCK_SIZE + (tl0 & 15)) * H_SZ + h) * D_SZ;
        const size_t b1 = (((size_t)s_bt[tl1 >> 4] * BLOCK_SIZE + (tl1 & 15)) * H_SZ + h) * D_SZ;
        const size_t b2 = (((size_t)s_bt[tl2 >> 4] * BLOCK_SIZE + (tl2 & 15)) * H_SZ + h) * D_SZ;
        const size_t b3 = (((size_t)s_bt[tl3 >> 4] * BLOCK_SIZE + (tl3 & 15)) * H_SZ + h) * D_SZ;

        const float4 k0 = __ldcs(((const float4*)(kcache + b0)) + lane);
        const float4 k1 = __ldcs(((const float4*)(kcache + b1)) + lane);
        const float4 k2 = __ldcs(((const float4*)(kcache + b2)) + lane);
        const float4 k3 = __ldcs(((const float4*)(kcache + b3)) + lane);
        const float4 v0 = __ldcs(((const float4*)(vcache + b0)) + lane);
        const float4 v1 = __ldcs(((const float4*)(vcache + b1)) + lane);
        const float4 v2 = __ldcs(((const float4*)(vcache + b2)) + lane);
        const float4 v3 = __ldcs(((const float4*)(vcache + b3)) + lane);

        float d0 = k0.x * qv.x + k0.y * qv.y + k0.z * qv.z + k0.w * qv.w;
        float d1 = k1.x * qv.x + k1.y * qv.y + k1.z * qv.z + k1.w * qv.w;
        float d2 = k2.x * qv.x + k2.y * qv.y + k2.z * qv.z + k2.w * qv.w;
        float d3 = k3.x * qv.x + k3.y * qv.y + k3.z * qv.z + k3.w * qv.w;
        d0 = warp_sum(d0) * SCALE;
        d1 = warp_sum(d1) * SCALE;
        d2 = warp_sum(d2) * SCALE;
        d3 = warp_sum(d3) * SCALE;

        const float nm = fmaxf(fmaxf(fmaxf(d0, d1), fmaxf(d2, d3)), m);
        const float c  = __expf(m - nm);
        const float p0 = __expf(d0 - nm);
        const float p1 = __expf(d1 - nm);
        const float p2 = __expf(d2 - nm);
        const float p3 = __expf(d3 - nm);
        l = l * c + (p0 + p1) + (p2 + p3);
        acc.x = acc.x * c + p0 * v0.x + p1 * v1.x + p2 * v2.x + p3 * v3.x;
        acc.y = acc.y * c + p0 * v0.y + p1 * v1.y + p2 * v2.y + p3 * v3.y;
        acc.z = acc.z * c + p0 * v0.z + p1 * v1.z + p2 * v2.z + p3 * v3.z;
        acc.w = acc.w * c + p0 * v0.w + p1 * v1.w + p2 * v2.w + p3 * v3.w;
        m = nm;
    }
    // remainder
    for (; t < c1; t += 8) {
        const int tl = t - c0;
        const size_t base = (((size_t)s_bt[tl >> 4] * BLOCK_SIZE + (tl & 15)) * H_SZ + h) * D_SZ;
        const float4 kk = __ldcs(((const float4*)(kcache + base)) + lane);
        const float4 vv = __ldcs(((const float4*)(vcache + base)) + lane);
        float d = warp_sum(kk.x * qv.x + kk.y * qv.y + kk.z * qv.z + kk.w * qv.w) * SCALE;
        const float nm = fmaxf(m, d);
        const float c = __expf(m - nm);
        const float p = __expf(d - nm);
        l = l * c + p;
        acc.x = acc.x * c + p * vv.x;
        acc.y = acc.y * c + p * vv.y;
        acc.z = acc.z * c + p * vv.z;
        acc.w = acc.w * c + p * vv.w;
        m = nm;
    }

    if (lane == 0) { s_m[warp] = m; s_l[warp] = l; }
    ((float4*)s_acc[warp])[lane] = acc;
    __syncthreads();

    // merge 8 warp-partials, write chunk partial to scratch
    if (tid < D_SZ) {
        float M = -CUDART_INF_F;
        #pragma unroll
        for (int w = 0; w < NUM_WARPS; ++w) M = fmaxf(M, s_m[w]);
        float L = 0.f, o = 0.f;
        #pragma unroll
        for (int w = 0; w < NUM_WARPS; ++w) {
            const float wgt = __expf(s_m[w] - M);
            L += wgt * s_l[w];
            o += wgt * s_acc[w][tid];
        }
        const int idx = ((b * H_SZ + h) * NSPLIT) + s;
        g_acc[idx][tid] = o;
        if (tid == 0) { g_m[idx] = M; g_l[idx] = L; }
    }
}

__global__ __launch_bounds__(128)
void paged_attn_reduce(const int* __restrict__ context_lens,
                       float* __restrict__ out) {
    const int bh = blockIdx.x;       // b*H + h
    const int b = bh / H_SZ;
    const int tid = threadIdx.x;     // output dim

    const int ctx = context_lens[b];
    const int ns = min(NSPLIT, (ctx + CHUNK - 1) / CHUNK);
    const int base = bh * NSPLIT;

    float M = -CUDART_INF_F;
    for (int s = 0; s < ns; ++s) M = fmaxf(M, g_m[base + s]);
    float L = 0.f, o = 0.f;
    for (int s = 0; s < ns; ++s) {
        const float wgt = __expf(g_m[base + s] - M);
        L += wgt * g_l[base + s];
        o += wgt * g_acc[base + s][tid];
    }
    out[(size_t)bh * D_SZ + tid] = o / L;
}

extern "C" void kernel_launch(void* const* d_in, const int* in_sizes, int n_in,
                              void* d_out, int out_size) {
    const float* q  = (const float*)d_in[0];
    const float* kc = (const float*)d_in[1];
    const float* vc = (const float*)d_in[2];
    const int* bt   = (const int*)d_in[3];
    const int* cl   = (const int*)d_in[4];
    float* out      = (float*)d_out;

    dim3 grid1(H_SZ, B_SZ, NSPLIT);
    paged_attn_partial<<<grid1, 256>>>(q, kc, vc, bt, cl);
    paged_attn_reduce<<<B_SZ * H_SZ, 128>>>(cl, out);
}